// round 5
// baseline (speedup 1.0000x reference)
#include <cuda_runtime.h>
#include <cuda_fp16.h>
#include <math.h>
#include <stdint.h>

// ---------------------------------------------------------------------------
// Problem constants (GRID fixed: [[1,48,48],[1,32,64],[2,24,40]])
// ---------------------------------------------------------------------------
#define NTOK    6272
#define DMODEL  1152
#define HEADS   16
#define HDIM    72
#define IDIM    4304
#define DOUT    2048
#define MROWS   1568
#define MD      4608
#define QKVW    3456

// ---------------------------------------------------------------------------
// Scratch
// ---------------------------------------------------------------------------
__device__ float g_x    [NTOK * DMODEL];
__device__ float g_h    [NTOK * DMODEL];
__device__ float g_qkv  [NTOK * QKVW];
__device__ float g_attn [NTOK * DMODEL];
__device__ float g_mlp  [NTOK * IDIM];
__device__ float g_cos  [NTOK * 36];
__device__ float g_sin  [NTOK * 36];

// ---------------------------------------------------------------------------
__device__ __forceinline__ void token_pos(int n, int& row, int& col, int& ih, int& iw)
{
    int local, h, w;
    if (n < 2304)      { local = n;          h = 48; w = 48; }
    else if (n < 4352) { local = n - 2304;   h = 32; w = 64; }
    else               { local = n - 4352;   h = 24; w = 40; }
    int rem = local % (h * w);
    int wb_cnt = w >> 1;
    int blk = rem >> 2, within = rem & 3;
    int hb = blk / wb_cnt, wb = blk % wb_cnt;
    row = hb * 2 + (within >> 1);
    col = wb * 2 + (within & 1);
    ih = h; iw = w;
}

__global__ void cossin_kernel()
{
    int idx = blockIdx.x * blockDim.x + threadIdx.x;
    if (idx >= NTOK * 36) return;
    int n = idx / 36, d = idx % 36;
    int row, col, ih, iw;
    token_pos(n, row, col, ih, iw);
    int j = (d < 18) ? d : d - 18;
    double p = (d < 18) ? (double)row : (double)col;
    double inv = 1.0 / pow(10000.0, (2.0 * (double)j) / 36.0);
    double ang = p * inv;
    g_cos[idx] = (float)cos(ang);
    g_sin[idx] = (float)sin(ang);
}

__global__ void posadd_kernel(const float* __restrict__ pos_table)
{
    int n = blockIdx.x;
    int row, col, ih, iw;
    token_pos(n, row, col, ih, iw);
    double hi = 47.0 * (double)row / (double)(ih - 1);
    double wi = 47.0 * (double)col / (double)(iw - 1);
    int hf = (int)floor(hi), wf = (int)floor(wi);
    float dh = (float)(hi - (double)hf), dw = (float)(wi - (double)wf);
    int hc = min(hf + 1, 47), wc = min(wf + 1, 47);
    float w00 = (1.f - dh) * (1.f - dw);
    float w01 = (1.f - dh) * dw;
    float w10 = dh * (1.f - dw);
    float w11 = dh * dw;
    const float* p00 = pos_table + (size_t)(hf * 48 + wf) * DMODEL;
    const float* p01 = pos_table + (size_t)(hf * 48 + wc) * DMODEL;
    const float* p10 = pos_table + (size_t)(hc * 48 + wf) * DMODEL;
    const float* p11 = pos_table + (size_t)(hc * 48 + wc) * DMODEL;
    float* xr = g_x + (size_t)n * DMODEL;
    for (int d = threadIdx.x; d < DMODEL; d += blockDim.x)
        xr[d] += p00[d] * w00 + p01[d] * w01 + p10[d] * w10 + p11[d] * w11;
}

__device__ __forceinline__ float warp_sum(float v)
{
#pragma unroll
    for (int o = 16; o > 0; o >>= 1) v += __shfl_xor_sync(0xffffffffu, v, o);
    return v;
}

__global__ void ln_kernel(const float* __restrict__ in, float* __restrict__ out,
                          const float* __restrict__ s, const float* __restrict__ b)
{
    __shared__ float sh[9];
    __shared__ float stat[2];
    int n = blockIdx.x;
    const float* xr = in + (size_t)n * DMODEL;
    int t = threadIdx.x, wid = t >> 5, lane = t & 31;

    float vals[4];
    float lsum = 0.f;
#pragma unroll
    for (int i = 0; i < 4; i++) { vals[i] = xr[t + i * 288]; lsum += vals[i]; }
    float ws = warp_sum(lsum);
    if (lane == 0) sh[wid] = ws;
    __syncthreads();
    if (t == 0) {
        float tot = 0.f;
#pragma unroll
        for (int i = 0; i < 9; i++) tot += sh[i];
        stat[0] = tot * (1.0f / DMODEL);
    }
    __syncthreads();
    float mu = stat[0];
    float lvar = 0.f;
#pragma unroll
    for (int i = 0; i < 4; i++) { float d = vals[i] - mu; lvar += d * d; }
    ws = warp_sum(lvar);
    __syncthreads();
    if (lane == 0) sh[wid] = ws;
    __syncthreads();
    if (t == 0) {
        float tot = 0.f;
#pragma unroll
        for (int i = 0; i < 9; i++) tot += sh[i];
        stat[1] = rsqrtf(tot * (1.0f / DMODEL) + 1e-6f);
    }
    __syncthreads();
    float r = stat[1];
    float* orow = out + (size_t)n * DMODEL;
#pragma unroll
    for (int i = 0; i < 4; i++) {
        int d = t + i * 288;
        orow[d] = (vals[i] - mu) * r * s[d] + b[d];
    }
}

__global__ void rope_kernel()
{
    int n = blockIdx.x;
    int t = threadIdx.x;
    int h = t / 36, d = t % 36;
    float c = g_cos[n * 36 + d];
    float s = g_sin[n * 36 + d];
    float* q = g_qkv + (size_t)n * QKVW + h * HDIM;
    float* k = q + DMODEL;
    float q0 = q[d], q1 = q[d + 36];
    q[d]      = q0 * c - q1 * s;
    q[d + 36] = q1 * c + q0 * s;
    float k0 = k[d], k1 = k[d + 36];
    k[d]      = k0 * c - k1 * s;
    k[d + 36] = k1 * c + k0 * s;
}

// ---------------------------------------------------------------------------
// fp16 helpers
// ---------------------------------------------------------------------------
__device__ __forceinline__ uint32_t pack_h2(float lo, float hi)
{
    __half2 h = __floats2half2_rn(lo, hi);
    return *reinterpret_cast<uint32_t*>(&h);
}

__device__ __forceinline__ void mma_f16(float c[4],
                                        uint32_t a0, uint32_t a1, uint32_t a2, uint32_t a3,
                                        uint32_t b0, uint32_t b1)
{
    asm volatile(
        "mma.sync.aligned.m16n8k16.row.col.f32.f16.f16.f32 "
        "{%0,%1,%2,%3}, {%4,%5,%6,%7}, {%8,%9}, {%0,%1,%2,%3};\n"
        : "+f"(c[0]), "+f"(c[1]), "+f"(c[2]), "+f"(c[3])
        : "r"(a0), "r"(a1), "r"(a2), "r"(a3), "r"(b0), "r"(b1));
}

__device__ __forceinline__ float gelu_tanh(float x)
{
    float x3 = x * x * x;
    return 0.5f * x * (1.f + tanhf(0.7978845608028654f * (x + 0.044715f * x3)));
}

// ---------------------------------------------------------------------------
// FP16 tensor-core GEMM (m16n8k16).  Block 256x128, BK=16, 8 warps (4Mx2N),
// warp tile 64x64.  Double-buffered smem of packed f16x2 words:
//   As [m][kk] stride 12  (kk = k/2; word = (k even, k odd)) -> banks 12g+q distinct
//   Bs [kk][n] stride 136 -> banks 8q+g distinct
// ---------------------------------------------------------------------------
#define EPI_BIAS      1
#define EPI_BIAS_GELU 2
#define EPI_BIAS_RES  3

#define GH_AST 12
#define GH_BST 136
#define GH_ASTAGE (256 * GH_AST)     // 3072 words
#define GH_BSTAGE (8 * GH_BST)       // 1088 words

template<int EPI>
__global__ void __launch_bounds__(256, 1)
gemm_h(const float* __restrict__ A, int lda,
       const float* __restrict__ B, int ldb,
       float* __restrict__ C, int ldc,
       const float* __restrict__ bias,
       const float* __restrict__ Res, int ldr,
       int Md, int Nd, int Kd)
{
    __shared__ uint32_t sm[2 * GH_ASTAGE + 2 * GH_BSTAGE];
    uint32_t* AsBase = sm;
    uint32_t* BsBase = sm + 2 * GH_ASTAGE;

    const int tid  = threadIdx.x;
    const int brow = blockIdx.y * 256;
    const int bcol = blockIdx.x * 128;
    const int w    = tid >> 5;
    const int lane = tid & 31;
    const int g    = lane >> 2;
    const int q    = lane & 3;
    const int wm   = w & 3;          // 4 warps in M
    const int wn   = w >> 2;         // 2 warps in N

    float acc[4][8][4];
#pragma unroll
    for (int i = 0; i < 4; i++)
#pragma unroll
        for (int j = 0; j < 8; j++)
#pragma unroll
            for (int r = 0; r < 4; r++) acc[i][j][r] = 0.f;

    // loader coordinates
    int am[4], ak2[4];
#pragma unroll
    for (int i = 0; i < 4; i++) {
        int s = tid + i * 256;
        am[i]  = s >> 2;             // m 0..255
        ak2[i] = (s & 3) * 2;        // word idx {0,2,4,6}; k4 = ak2*2
    }
    const int bkk = tid >> 5;        // 0..7
    const int bn4 = (tid & 31) * 4;  // 0..124
    const int bngood = (bcol + bn4) < Nd;

    float4 av[4], bv0, bv1;
    // prologue (k0 = 0)
#pragma unroll
    for (int i = 0; i < 4; i++) {
        int gr = brow + am[i];
        av[i] = make_float4(0.f, 0.f, 0.f, 0.f);
        if (gr < Md)
            av[i] = *reinterpret_cast<const float4*>(A + (long long)gr * lda + ak2[i] * 2);
    }
    bv0 = make_float4(0.f, 0.f, 0.f, 0.f);
    bv1 = bv0;
    if (bngood) {
        bv0 = *reinterpret_cast<const float4*>(B + (long long)(2 * bkk    ) * ldb + bcol + bn4);
        bv1 = *reinterpret_cast<const float4*>(B + (long long)(2 * bkk + 1) * ldb + bcol + bn4);
    }
    // store stage 0
#pragma unroll
    for (int i = 0; i < 4; i++) {
        uint2 t = make_uint2(pack_h2(av[i].x, av[i].y), pack_h2(av[i].z, av[i].w));
        *reinterpret_cast<uint2*>(&AsBase[am[i] * GH_AST + ak2[i]]) = t;
    }
    {
        uint4 t = make_uint4(pack_h2(bv0.x, bv1.x), pack_h2(bv0.y, bv1.y),
                             pack_h2(bv0.z, bv1.z), pack_h2(bv0.w, bv1.w));
        *reinterpret_cast<uint4*>(&BsBase[bkk * GH_BST + bn4]) = t;
    }
    __syncthreads();

    const int ntiles = Kd >> 4;
    for (int kt = 0; kt < ntiles; kt++) {
        const int buf = kt & 1;
        const bool more = (kt + 1 < ntiles);
        if (more) {
            int k0 = (kt + 1) << 4;
#pragma unroll
            for (int i = 0; i < 4; i++) {
                int gr = brow + am[i];
                av[i] = make_float4(0.f, 0.f, 0.f, 0.f);
                if (gr < Md)
                    av[i] = *reinterpret_cast<const float4*>(A + (long long)gr * lda + k0 + ak2[i] * 2);
            }
            bv0 = make_float4(0.f, 0.f, 0.f, 0.f);
            bv1 = bv0;
            if (bngood) {
                bv0 = *reinterpret_cast<const float4*>(B + (long long)(k0 + 2 * bkk    ) * ldb + bcol + bn4);
                bv1 = *reinterpret_cast<const float4*>(B + (long long)(k0 + 2 * bkk + 1) * ldb + bcol + bn4);
            }
        }

        const uint32_t* Ab = AsBase + buf * GH_ASTAGE;
        const uint32_t* Bb = BsBase + buf * GH_BSTAGE;

        uint32_t afr[4][4], bfr[8][2];
#pragma unroll
        for (int mt = 0; mt < 4; mt++) {
            int mb = wm * 64 + mt * 16;
            afr[mt][0] = Ab[(mb + g    ) * GH_AST + q    ];
            afr[mt][1] = Ab[(mb + g + 8) * GH_AST + q    ];
            afr[mt][2] = Ab[(mb + g    ) * GH_AST + q + 4];
            afr[mt][3] = Ab[(mb + g + 8) * GH_AST + q + 4];
        }
#pragma unroll
        for (int nt = 0; nt < 8; nt++) {
            int nb = wn * 64 + nt * 8;
            bfr[nt][0] = Bb[(q    ) * GH_BST + nb + g];
            bfr[nt][1] = Bb[(q + 4) * GH_BST + nb + g];
        }
#pragma unroll
        for (int mt = 0; mt < 4; mt++)
#pragma unroll
            for (int nt = 0; nt < 8; nt++)
                mma_f16(acc[mt][nt],
                        afr[mt][0], afr[mt][1], afr[mt][2], afr[mt][3],
                        bfr[nt][0], bfr[nt][1]);

        if (more) {
            uint32_t* An = AsBase + (buf ^ 1) * GH_ASTAGE;
            uint32_t* Bn = BsBase + (buf ^ 1) * GH_BSTAGE;
#pragma unroll
            for (int i = 0; i < 4; i++) {
                uint2 t = make_uint2(pack_h2(av[i].x, av[i].y), pack_h2(av[i].z, av[i].w));
                *reinterpret_cast<uint2*>(&An[am[i] * GH_AST + ak2[i]]) = t;
            }
            uint4 t = make_uint4(pack_h2(bv0.x, bv1.x), pack_h2(bv0.y, bv1.y),
                                 pack_h2(bv0.z, bv1.z), pack_h2(bv0.w, bv1.w));
            *reinterpret_cast<uint4*>(&Bn[bkk * GH_BST + bn4]) = t;
        }
        __syncthreads();
    }

    // epilogue
#pragma unroll
    for (int mt = 0; mt < 4; mt++) {
#pragma unroll
        for (int half = 0; half < 2; half++) {
            int r = brow + wm * 64 + mt * 16 + g + 8 * half;
            if (r >= Md) continue;
#pragma unroll
            for (int nt = 0; nt < 8; nt++) {
                int c = bcol + wn * 64 + nt * 8 + 2 * q;
                if (c + 1 >= Nd) {
                    if (c < Nd) {
                        float v = acc[mt][nt][half * 2];
                        if (EPI >= EPI_BIAS)      v += bias[c];
                        if (EPI == EPI_BIAS_GELU) v = gelu_tanh(v);
                        if (EPI == EPI_BIAS_RES)  v += Res[(long long)r * ldr + c];
                        C[(long long)r * ldc + c] = v;
                    }
                    continue;
                }
                float v0 = acc[mt][nt][half * 2];
                float v1 = acc[mt][nt][half * 2 + 1];
                if (EPI >= EPI_BIAS)      { v0 += bias[c]; v1 += bias[c + 1]; }
                if (EPI == EPI_BIAS_GELU) { v0 = gelu_tanh(v0); v1 = gelu_tanh(v1); }
                if (EPI == EPI_BIAS_RES)  {
                    v0 += Res[(long long)r * ldr + c];
                    v1 += Res[(long long)r * ldr + c + 1];
                }
                *reinterpret_cast<float2*>(C + (long long)r * ldc + c) = make_float2(v0, v1);
            }
        }
    }
}

// ---------------------------------------------------------------------------
// Fused flash attention, fp16 m16n8k16, online softmax (fp32 stats).
//   CTA = 128 q-rows x 1 head, KV tiles of 64.  hdim padded 72 -> 80 (zeros).
//   Packed f16x2 smem layouts (word = k-pair):
//     Qs [row][kk]  stride 44   (A of QK)
//     Ks [kk][kv]   stride 72   (B of QK)
//     Ps [row][kvk] stride 36   (A of PV)
//     Vs [kvk][hd]  stride 104  (B of PV)
// ---------------------------------------------------------------------------
#define QS_OFF   0
#define QS_ST    44
#define KS_OFF   (QS_OFF + 128 * QS_ST)      // 5632
#define KS_ST    72
#define VS_OFF   (KS_OFF + 40 * KS_ST)       // 8512
#define VS_ST    104
#define PS_OFF   (VS_OFF + 32 * VS_ST)       // 11840
#define PS_ST    36
#define MS_OFF   (PS_OFF + 128 * PS_ST)      // 16448
#define LS_OFF   (MS_OFF + 128)
#define AL_OFF   (LS_OFF + 128)
#define RED_OFF  (AL_OFF + 128)
#define FA_WORDS (RED_OFF + 512)             // 17344
#define FA_BYTES (FA_WORDS * 4)              // 69376

__global__ void __launch_bounds__(256, 1)
flash_attn(const float* __restrict__ qkv, float* __restrict__ attn)
{
    extern __shared__ uint32_t smem[];
    uint32_t* Qs = smem + QS_OFF;
    uint32_t* Ks = smem + KS_OFF;
    uint32_t* Vs = smem + VS_OFF;
    uint32_t* Ps = smem + PS_OFF;
    float* m_s  = (float*)(smem + MS_OFF);
    float* l_s  = (float*)(smem + LS_OFF);
    float* al_s = (float*)(smem + AL_OFF);
    float* red  = (float*)(smem + RED_OFF);

    int t = blockIdx.x;
    int head = blockIdx.y;
    int st, S, q0;
    if (t < 18)      { st = 0;    S = 2304; q0 = t * 128; }
    else if (t < 34) { st = 2304; S = 2048; q0 = (t - 18) * 128; }
    else if (t < 42) { st = 4352; S = 960;  q0 = (t - 34) * 128; }
    else             { st = 5312; S = 960;  q0 = (t - 42) * 128; }

    const int tid = threadIdx.x;
    const int w = tid >> 5, lane = tid & 31;
    const int g = lane >> 2, q = lane & 3;
    const int wm  = w & 1, wn  = w >> 1;   // QK warp grid 2(M) x 4(N), 64x16
    const int wm2 = w & 3, wn2 = w >> 2;   // PV warp grid 4(M) x 2(N), 32x40

    const float scale = 0.11785113019775793f;

    // ---- Q tile: Qs[row][kk], plus zero hdim pad kk 36..39
    for (int s = tid; s < 128 * 18; s += 256) {
        int row = s / 18, h4 = (s % 18) * 4;
        float4 v = make_float4(0.f, 0.f, 0.f, 0.f);
        if (q0 + row < S)
            v = *reinterpret_cast<const float4*>(
                qkv + (size_t)(st + q0 + row) * QKVW + head * HDIM + h4);
        uint2 tw = make_uint2(pack_h2(v.x, v.y), pack_h2(v.z, v.w));
        *reinterpret_cast<uint2*>(&Qs[row * QS_ST + h4 / 2]) = tw;
    }
    for (int s = tid; s < 512; s += 256) {          // Q pad
        int row = s >> 2, kk = 36 + (s & 3);
        Qs[row * QS_ST + kk] = 0;
    }
    if (tid < 256) {                                 // K pad (kk 36..39 x 64 kv)
        Ks[(36 + (tid >> 6)) * KS_ST + (tid & 63)] = 0;
    }
    if (tid < 256) {                                 // V pad (hd 72..79 x 32 rows)
        Vs[(tid >> 3) * VS_ST + 72 + (tid & 7)] = 0;
    }
    if (tid < 128) { m_s[tid] = -1e30f; l_s[tid] = 0.f; }

    float O[2][5][4];
#pragma unroll
    for (int i = 0; i < 2; i++)
#pragma unroll
        for (int j = 0; j < 5; j++)
#pragma unroll
            for (int r = 0; r < 4; r++) O[i][j][r] = 0.f;

    const int nkv = S >> 6;
    for (int j = 0; j < nkv; j++) {
        __syncthreads();
        const int kv0 = j * 64;
        // K tile -> Ks[kk][kv]
        for (int s = tid; s < 64 * 18; s += 256) {
            int kv = s / 18, h4 = (s % 18) * 4;
            float4 v = *reinterpret_cast<const float4*>(
                qkv + (size_t)(st + kv0 + kv) * QKVW + DMODEL + head * HDIM + h4);
            Ks[(h4 / 2    ) * KS_ST + kv] = pack_h2(v.x, v.y);
            Ks[(h4 / 2 + 1) * KS_ST + kv] = pack_h2(v.z, v.w);
        }
        // V tile -> Vs[kv/2][hd] halfwords
        for (int s = tid; s < 64 * 18; s += 256) {
            int kv = s / 18, h4 = (s % 18) * 4;
            float4 v = *reinterpret_cast<const float4*>(
                qkv + (size_t)(st + kv0 + kv) * QKVW + 2 * DMODEL + head * HDIM + h4);
            uint16_t* Vh = reinterpret_cast<uint16_t*>(Vs);
            int base = ((kv >> 1) * VS_ST + h4) * 2 + (kv & 1);
            __half hx = __float2half_rn(v.x), hy = __float2half_rn(v.y);
            __half hz = __float2half_rn(v.z), hw = __float2half_rn(v.w);
            Vh[base    ] = *reinterpret_cast<uint16_t*>(&hx);
            Vh[base + 2] = *reinterpret_cast<uint16_t*>(&hy);
            Vh[base + 4] = *reinterpret_cast<uint16_t*>(&hz);
            Vh[base + 6] = *reinterpret_cast<uint16_t*>(&hw);
        }
        __syncthreads();

        // ---- S = scale * Q @ K^T  (5 ksteps of k16 over padded hdim 80)
        float acc_s[4][2][4];
#pragma unroll
        for (int a = 0; a < 4; a++)
#pragma unroll
            for (int b = 0; b < 2; b++)
#pragma unroll
                for (int r = 0; r < 4; r++) acc_s[a][b][r] = 0.f;

#pragma unroll
        for (int i = 0; i < 5; i++) {
            int kb = i * 8;
            uint32_t af[4][4], bf[2][2];
#pragma unroll
            for (int mt = 0; mt < 4; mt++) {
                int mb = wm * 64 + mt * 16;
                af[mt][0] = Qs[(mb + g    ) * QS_ST + kb + q    ];
                af[mt][1] = Qs[(mb + g + 8) * QS_ST + kb + q    ];
                af[mt][2] = Qs[(mb + g    ) * QS_ST + kb + q + 4];
                af[mt][3] = Qs[(mb + g + 8) * QS_ST + kb + q + 4];
            }
#pragma unroll
            for (int nt = 0; nt < 2; nt++) {
                int nb = wn * 16 + nt * 8;
                bf[nt][0] = Ks[(kb + q    ) * KS_ST + nb + g];
                bf[nt][1] = Ks[(kb + q + 4) * KS_ST + nb + g];
            }
#pragma unroll
            for (int mt = 0; mt < 4; mt++)
#pragma unroll
                for (int nt = 0; nt < 2; nt++)
                    mma_f16(acc_s[mt][nt],
                            af[mt][0], af[mt][1], af[mt][2], af[mt][3],
                            bf[nt][0], bf[nt][1]);
        }
#pragma unroll
        for (int a = 0; a < 4; a++)
#pragma unroll
            for (int b = 0; b < 2; b++)
#pragma unroll
                for (int r = 0; r < 4; r++) acc_s[a][b][r] *= scale;

        // ---- row max
#pragma unroll
        for (int mt = 0; mt < 4; mt++) {
#pragma unroll
            for (int h = 0; h < 2; h++) {
                float rmx = fmaxf(fmaxf(acc_s[mt][0][2 * h], acc_s[mt][0][2 * h + 1]),
                                  fmaxf(acc_s[mt][1][2 * h], acc_s[mt][1][2 * h + 1]));
                rmx = fmaxf(rmx, __shfl_xor_sync(0xffffffffu, rmx, 1));
                rmx = fmaxf(rmx, __shfl_xor_sync(0xffffffffu, rmx, 2));
                if (q == 0)
                    red[wn * 128 + wm * 64 + mt * 16 + g + 8 * h] = rmx;
            }
        }
        __syncthreads();
        if (tid < 128) {
            float tm = fmaxf(fmaxf(red[tid], red[128 + tid]),
                             fmaxf(red[256 + tid], red[384 + tid]));
            float mo = m_s[tid];
            float mn = fmaxf(mo, tm);
            al_s[tid] = __expf(mo - mn);
            m_s[tid]  = mn;
        }
        __syncthreads();

        // ---- P~ = exp(S - m) -> Ps (f16x2 words along kv); row sums
#pragma unroll
        for (int mt = 0; mt < 4; mt++) {
#pragma unroll
            for (int h = 0; h < 2; h++) {
                int row = wm * 64 + mt * 16 + g + 8 * h;
                float mn = m_s[row];
                float rs = 0.f;
#pragma unroll
                for (int nt = 0; nt < 2; nt++) {
                    int nb = wn * 16 + nt * 8;
                    float p0 = __expf(acc_s[mt][nt][2 * h    ] - mn);
                    float p1 = __expf(acc_s[mt][nt][2 * h + 1] - mn);
                    rs += p0 + p1;
                    Ps[row * PS_ST + (nb >> 1) + q] = pack_h2(p0, p1);
                }
                rs += __shfl_xor_sync(0xffffffffu, rs, 1);
                rs += __shfl_xor_sync(0xffffffffu, rs, 2);
                if (q == 0) red[wn * 128 + row] = rs;
            }
        }
        // rescale O by alpha
#pragma unroll
        for (int mt = 0; mt < 2; mt++) {
#pragma unroll
            for (int h = 0; h < 2; h++) {
                int row = wm2 * 32 + mt * 16 + g + 8 * h;
                float a = al_s[row];
#pragma unroll
                for (int nt = 0; nt < 5; nt++) {
                    O[mt][nt][2 * h + 0] *= a;
                    O[mt][nt][2 * h + 1] *= a;
                }
            }
        }
        __syncthreads();
        if (tid < 128)
            l_s[tid] = l_s[tid] * al_s[tid] +
                       red[tid] + red[128 + tid] + red[256 + tid] + red[384 + tid];

        // ---- O += P~ @ V  (4 ksteps of k16 over kv 64)
#pragma unroll
        for (int i = 0; i < 4; i++) {
            int kb = i * 8;
            uint32_t af[2][4], bf[5][2];
#pragma unroll
            for (int mt = 0; mt < 2; mt++) {
                int mb = wm2 * 32 + mt * 16;
                af[mt][0] = Ps[(mb + g    ) * PS_ST + kb + q    ];
                af[mt][1] = Ps[(mb + g + 8) * PS_ST + kb + q    ];
                af[mt][2] = Ps[(mb + g    ) * PS_ST + kb + q + 4];
                af[mt][3] = Ps[(mb + g + 8) * PS_ST + kb + q + 4];
            }
#pragma unroll
            for (int nt = 0; nt < 5; nt++) {
                int nb = wn2 * 40 + nt * 8;
                bf[nt][0] = Vs[(kb + q    ) * VS_ST + nb + g];
                bf[nt][1] = Vs[(kb + q + 4) * VS_ST + nb + g];
            }
#pragma unroll
            for (int mt = 0; mt < 2; mt++)
#pragma unroll
                for (int nt = 0; nt < 5; nt++)
                    mma_f16(O[mt][nt],
                            af[mt][0], af[mt][1], af[mt][2], af[mt][3],
                            bf[nt][0], bf[nt][1]);
        }
    }
    __syncthreads();

    // ---- epilogue
#pragma unroll
    for (int mt = 0; mt < 2; mt++) {
#pragma unroll
        for (int h = 0; h < 2; h++) {
            int r = wm2 * 32 + mt * 16 + g + 8 * h;
            if (q0 + r >= S) continue;
            float inv = 1.0f / l_s[r];
#pragma unroll
            for (int nt = 0; nt < 5; nt++) {
#pragma unroll
                for (int e = 0; e < 2; e++) {
                    int c = wn2 * 40 + nt * 8 + 2 * q + e;
                    if (c < HDIM)
                        attn[(size_t)(st + q0 + r) * DMODEL + head * HDIM + c] =
                            O[mt][nt][2 * h + e] * inv;
                }
            }
        }
    }
}

// ---------------------------------------------------------------------------
// Host launcher
// ---------------------------------------------------------------------------
#define SYM(p, s) do { void* _t; cudaGetSymbolAddress(&_t, s); p = (float*)_t; } while (0)

static inline dim3 ggridh(int Md, int Nd) {
    return dim3((Nd + 127) / 128, (Md + 255) / 256);
}

extern "C" void kernel_launch(void* const* d_in, const int* in_sizes, int n_in,
                              void* d_out, int out_size)
{
    (void)in_sizes; (void)n_in; (void)out_size;
    const float* pixel    = (const float*)d_in[0];
    const float* patch_w  = (const float*)d_in[2];
    const float* patch_b  = (const float*)d_in[3];
    const float* pos_tab  = (const float*)d_in[4];
    const float* ln1_s    = (const float*)d_in[5];
    const float* ln1_b    = (const float*)d_in[6];
    const float* qkv_w    = (const float*)d_in[7];
    const float* qkv_b    = (const float*)d_in[8];
    const float* proj_w   = (const float*)d_in[9];
    const float* proj_b   = (const float*)d_in[10];
    const float* ln2_s    = (const float*)d_in[11];
    const float* ln2_b    = (const float*)d_in[12];
    const float* fc1_w    = (const float*)d_in[13];
    const float* fc1_b    = (const float*)d_in[14];
    const float* fc2_w    = (const float*)d_in[15];
    const float* fc2_b    = (const float*)d_in[16];
    const float* m_ln_s   = (const float*)d_in[17];
    const float* m_ln_b   = (const float*)d_in[18];
    const float* m_fc1_w  = (const float*)d_in[19];
    const float* m_fc1_b  = (const float*)d_in[20];
    const float* m_fc2_w  = (const float*)d_in[21];
    const float* m_fc2_b  = (const float*)d_in[22];
    float* out = (float*)d_out;

    float *x, *h, *qkv, *attn, *mlp;
    SYM(x, g_x); SYM(h, g_h); SYM(qkv, g_qkv); SYM(attn, g_attn);
    SYM(mlp, g_mlp);

    static bool attr_set = false;
    if (!attr_set) {
        cudaFuncSetAttribute(flash_attn,
                             cudaFuncAttributeMaxDynamicSharedMemorySize, FA_BYTES);
        attr_set = true;
    }

    cossin_kernel<<<(NTOK * 36 + 255) / 256, 256>>>();

    // Patch embed
    gemm_h<EPI_BIAS><<<ggridh(NTOK, DMODEL), 256>>>(
        pixel, 1536, patch_w, DMODEL, x, DMODEL,
        patch_b, nullptr, 0, NTOK, DMODEL, 1536);

    posadd_kernel<<<NTOK, 288>>>(pos_tab);

    for (int l = 0; l < 2; l++) {
        const float* l1s = ln1_s + l * DMODEL;
        const float* l1b = ln1_b + l * DMODEL;
        const float* qw  = qkv_w + (size_t)l * DMODEL * QKVW;
        const float* qb  = qkv_b + (size_t)l * QKVW;
        const float* pw  = proj_w + (size_t)l * DMODEL * DMODEL;
        const float* pb  = proj_b + (size_t)l * DMODEL;
        const float* l2s = ln2_s + l * DMODEL;
        const float* l2b = ln2_b + l * DMODEL;
        const float* f1w = fc1_w + (size_t)l * DMODEL * IDIM;
        const float* f1b = fc1_b + (size_t)l * IDIM;
        const float* f2w = fc2_w + (size_t)l * IDIM * DMODEL;
        const float* f2b = fc2_b + (size_t)l * DMODEL;

        ln_kernel<<<NTOK, 288>>>(x, h, l1s, l1b);

        gemm_h<EPI_BIAS><<<ggridh(NTOK, QKVW), 256>>>(
            h, DMODEL, qw, QKVW, qkv, QKVW,
            qb, nullptr, 0, NTOK, QKVW, DMODEL);

        rope_kernel<<<NTOK, 576>>>();

        flash_attn<<<dim3(50, HEADS), 256, FA_BYTES>>>(qkv, attn);

        gemm_h<EPI_BIAS_RES><<<ggridh(NTOK, DMODEL), 256>>>(
            attn, DMODEL, pw, DMODEL, x, DMODEL,
            pb, x, DMODEL, NTOK, DMODEL, DMODEL);

        ln_kernel<<<NTOK, 288>>>(x, h, l2s, l2b);

        gemm_h<EPI_BIAS_GELU><<<ggridh(NTOK, IDIM), 256>>>(
            h, DMODEL, f1w, IDIM, mlp, IDIM,
            f1b, nullptr, 0, NTOK, IDIM, DMODEL);

        gemm_h<EPI_BIAS_RES><<<ggridh(NTOK, DMODEL), 256>>>(
            mlp, IDIM, f2w, DMODEL, x, DMODEL,
            f2b, x, DMODEL, NTOK, DMODEL, IDIM);
    }

    // merger
    ln_kernel<<<NTOK, 288>>>(x, h, m_ln_s, m_ln_b);

    gemm_h<EPI_BIAS_GELU><<<ggridh(MROWS, MD), 256>>>(
        h, MD, m_fc1_w, MD, mlp, MD,
        m_fc1_b, nullptr, 0, MROWS, MD, MD);

    gemm_h<EPI_BIAS><<<ggridh(MROWS, DOUT), 256>>>(
        mlp, MD, m_fc2_w, DOUT, out, DOUT,
        m_fc2_b, nullptr, 0, MROWS, DOUT, MD);
}

// round 6
// speedup vs baseline: 2.1953x; 2.1953x over previous
#include <cuda_runtime.h>
#include <cuda_fp16.h>
#include <math.h>
#include <stdint.h>

// ---------------------------------------------------------------------------
// Problem constants (GRID fixed: [[1,48,48],[1,32,64],[2,24,40]])
// ---------------------------------------------------------------------------
#define NTOK    6272
#define DMODEL  1152
#define HEADS   16
#define HDIM    72
#define IDIM    4304
#define DOUT    2048
#define MROWS   1568
#define MD4     4608
#define QKVW    3456
#define CIN     1536

// ---------------------------------------------------------------------------
// Scratch buffers
// ---------------------------------------------------------------------------
__device__ float  g_x    [NTOK * DMODEL];        // residual (fp32)
__device__ __half g_pix  [NTOK * CIN];           // pixel fp16
__device__ __half g_hh   [NTOK * DMODEL];        // LN out fp16
__device__ __half g_qkvh [NTOK * QKVW];          // qkv fp16
__device__ __half g_attnh[NTOK * DMODEL];        // attn out fp16
__device__ __half g_mlph [NTOK * IDIM];          // mlp hidden fp16
__device__ float  g_cos  [NTOK * 36];
__device__ float  g_sin  [NTOK * 36];

// transposed fp16 weights, packed
#define SZ_PATCH (1152ULL * 1536)
#define SZ_QKV   (3456ULL * 1152)
#define SZ_PROJ  (1152ULL * 1152)
#define SZ_FC1   (4304ULL * 1152)
#define SZ_FC2   (1152ULL * 4304)
#define SZ_MFC1  (4608ULL * 4608)
#define SZ_MFC2  (2048ULL * 4608)
#define OFF_PATCH 0ULL
#define OFF_QKV   (OFF_PATCH + SZ_PATCH)
#define OFF_PROJ  (OFF_QKV + 2 * SZ_QKV)
#define OFF_FC1   (OFF_PROJ + 2 * SZ_PROJ)
#define OFF_FC2   (OFF_FC1 + 2 * SZ_FC1)
#define OFF_MFC1  (OFF_FC2 + 2 * SZ_FC2)
#define OFF_MFC2  (OFF_MFC1 + SZ_MFC1)
#define WT_TOTAL  (OFF_MFC2 + SZ_MFC2)
__device__ __half g_wt[WT_TOTAL];

// ---------------------------------------------------------------------------
__device__ __forceinline__ void token_pos(int n, int& row, int& col, int& ih, int& iw)
{
    int local, h, w;
    if (n < 2304)      { local = n;          h = 48; w = 48; }
    else if (n < 4352) { local = n - 2304;   h = 32; w = 64; }
    else               { local = n - 4352;   h = 24; w = 40; }
    int rem = local % (h * w);
    int wb_cnt = w >> 1;
    int blk = rem >> 2, within = rem & 3;
    int hb = blk / wb_cnt, wb = blk % wb_cnt;
    row = hb * 2 + (within >> 1);
    col = wb * 2 + (within & 1);
    ih = h; iw = w;
}

__global__ void cossin_kernel()
{
    int idx = blockIdx.x * blockDim.x + threadIdx.x;
    if (idx >= NTOK * 36) return;
    int n = idx / 36, d = idx % 36;
    int row, col, ih, iw;
    token_pos(n, row, col, ih, iw);
    int j = (d < 18) ? d : d - 18;
    double p = (d < 18) ? (double)row : (double)col;
    double inv = 1.0 / pow(10000.0, (2.0 * (double)j) / 36.0);
    double ang = p * inv;
    g_cos[idx] = (float)cos(ang);
    g_sin[idx] = (float)sin(ang);
}

__global__ void posadd_kernel(const float* __restrict__ pos_table)
{
    int n = blockIdx.x;
    int row, col, ih, iw;
    token_pos(n, row, col, ih, iw);
    double hi = 47.0 * (double)row / (double)(ih - 1);
    double wi = 47.0 * (double)col / (double)(iw - 1);
    int hf = (int)floor(hi), wf = (int)floor(wi);
    float dh = (float)(hi - (double)hf), dw = (float)(wi - (double)wf);
    int hc = min(hf + 1, 47), wc = min(wf + 1, 47);
    float w00 = (1.f - dh) * (1.f - dw);
    float w01 = (1.f - dh) * dw;
    float w10 = dh * (1.f - dw);
    float w11 = dh * dw;
    const float* p00 = pos_table + (size_t)(hf * 48 + wf) * DMODEL;
    const float* p01 = pos_table + (size_t)(hf * 48 + wc) * DMODEL;
    const float* p10 = pos_table + (size_t)(hc * 48 + wf) * DMODEL;
    const float* p11 = pos_table + (size_t)(hc * 48 + wc) * DMODEL;
    float* xr = g_x + (size_t)n * DMODEL;
    for (int d = threadIdx.x; d < DMODEL; d += blockDim.x)
        xr[d] += p00[d] * w00 + p01[d] * w01 + p10[d] * w10 + p11[d] * w11;
}

// fp32 -> fp16 elementwise
__global__ void conv_h(const float* __restrict__ in, __half* __restrict__ out, int n)
{
    int i = blockIdx.x * blockDim.x + threadIdx.x;
    if (i < n) out[i] = __float2half_rn(in[i]);
}

// W [K,N] fp32 -> Wt [N,K] fp16 (tiled transpose)
__global__ void wt_t(const float* __restrict__ W, __half* __restrict__ Wt, int K, int N)
{
    __shared__ float tile[32][33];
    int nt = blockIdx.x * 32, kt = blockIdx.y * 32;
    int tx = threadIdx.x, ty = threadIdx.y;
#pragma unroll
    for (int j = 0; j < 4; j++) {
        int k = kt + ty + j * 8;
        if (k < K && nt + tx < N)
            tile[ty + j * 8][tx] = W[(size_t)k * N + nt + tx];
    }
    __syncthreads();
#pragma unroll
    for (int j = 0; j < 4; j++) {
        int n = nt + ty + j * 8;
        if (n < N && kt + tx < K)
            Wt[(size_t)n * K + kt + tx] = __float2half_rn(tile[tx][ty + j * 8]);
    }
}

__device__ __forceinline__ float warp_sum(float v)
{
#pragma unroll
    for (int o = 16; o > 0; o >>= 1) v += __shfl_xor_sync(0xffffffffu, v, o);
    return v;
}

// LayerNorm fp32 in -> fp16 out
__global__ void ln_h(const float* __restrict__ in, __half* __restrict__ out,
                     const float* __restrict__ s, const float* __restrict__ b)
{
    __shared__ float sh[9];
    __shared__ float stat[2];
    int n = blockIdx.x;
    const float* xr = in + (size_t)n * DMODEL;
    int t = threadIdx.x, wid = t >> 5, lane = t & 31;

    float vals[4];
    float lsum = 0.f;
#pragma unroll
    for (int i = 0; i < 4; i++) { vals[i] = xr[t + i * 288]; lsum += vals[i]; }
    float ws = warp_sum(lsum);
    if (lane == 0) sh[wid] = ws;
    __syncthreads();
    if (t == 0) {
        float tot = 0.f;
#pragma unroll
        for (int i = 0; i < 9; i++) tot += sh[i];
        stat[0] = tot * (1.0f / DMODEL);
    }
    __syncthreads();
    float mu = stat[0];
    float lvar = 0.f;
#pragma unroll
    for (int i = 0; i < 4; i++) { float d = vals[i] - mu; lvar += d * d; }
    ws = warp_sum(lvar);
    __syncthreads();
    if (lane == 0) sh[wid] = ws;
    __syncthreads();
    if (t == 0) {
        float tot = 0.f;
#pragma unroll
        for (int i = 0; i < 9; i++) tot += sh[i];
        stat[1] = rsqrtf(tot * (1.0f / DMODEL) + 1e-6f);
    }
    __syncthreads();
    float r = stat[1];
    __half* orow = out + (size_t)n * DMODEL;
#pragma unroll
    for (int i = 0; i < 4; i++) {
        int d = t + i * 288;
        orow[d] = __float2half_rn((vals[i] - mu) * r * s[d] + b[d]);
    }
}

// RoPE in-place on fp16 qkv
__global__ void rope_h()
{
    int n = blockIdx.x;
    int t = threadIdx.x;
    int h = t / 36, d = t % 36;
    float c = g_cos[n * 36 + d];
    float s = g_sin[n * 36 + d];
    __half* q = g_qkvh + (size_t)n * QKVW + h * HDIM;
    __half* k = q + DMODEL;
    float q0 = __half2float(q[d]), q1 = __half2float(q[d + 36]);
    q[d]      = __float2half_rn(q0 * c - q1 * s);
    q[d + 36] = __float2half_rn(q1 * c + q0 * s);
    float k0 = __half2float(k[d]), k1 = __half2float(k[d + 36]);
    k[d]      = __float2half_rn(k0 * c - k1 * s);
    k[d + 36] = __float2half_rn(k1 * c + k0 * s);
}

// ---------------------------------------------------------------------------
// mma / misc helpers
// ---------------------------------------------------------------------------
__device__ __forceinline__ void mma_f16(float c[4],
                                        uint32_t a0, uint32_t a1, uint32_t a2, uint32_t a3,
                                        uint32_t b0, uint32_t b1)
{
    asm volatile(
        "mma.sync.aligned.m16n8k16.row.col.f32.f16.f16.f32 "
        "{%0,%1,%2,%3}, {%4,%5,%6,%7}, {%8,%9}, {%0,%1,%2,%3};\n"
        : "+f"(c[0]), "+f"(c[1]), "+f"(c[2]), "+f"(c[3])
        : "r"(a0), "r"(a1), "r"(a2), "r"(a3), "r"(b0), "r"(b1));
}

__device__ __forceinline__ float gelu_tanh(float x)
{
    float x3 = x * x * x;
    return 0.5f * x * (1.f + tanhf(0.7978845608028654f * (x + 0.044715f * x3)));
}

__device__ __forceinline__ uint32_t pack_h2(float lo, float hi)
{
    __half2 h = __floats2half2_rn(lo, hi);
    return *reinterpret_cast<uint32_t*>(&h);
}

// ---------------------------------------------------------------------------
// GEMM v3: A fp16 [M,K] row-major, Bt fp16 [N,K] row-major, C fp32 or fp16.
//   Block 128x128, BK=16, 4 stages, cp.async + ldmatrix.
//   8 warps 2(M) x 4(N): warp tile 64x32.
//   smem rows padded to 24 halfs (12 words): ldmatrix phases hit all 32 banks.
// ---------------------------------------------------------------------------
#define EPI_BIAS      1
#define EPI_BIAS_GELU 2
#define EPI_BIAS_RES  3

template<int EPI, bool OUTH>
__global__ void __launch_bounds__(256)
gemm3(const __half* __restrict__ A, int lda,
      const __half* __restrict__ Bt, int ldb,
      void* __restrict__ Cv, int ldc,
      const float* __restrict__ bias,
      const float* __restrict__ Res, int ldr,
      int Md, int Nd, int Kd)
{
    __shared__ uint32_t smbuf[4 * 3072];     // 48 KB: 4 stages x (A 1536w + B 1536w)

    const int tid  = threadIdx.x;
    const int brow = blockIdx.y * 128;
    const int bcol = blockIdx.x * 128;
    const int w    = tid >> 5;
    const int lane = tid & 31;
    const int g    = lane >> 2;
    const int q    = lane & 3;
    const int wm   = w & 1;                  // 2 warps M
    const int wn   = w >> 1;                 // 4 warps N

    // cp.async coords: one A chunk + one B chunk (16B) per thread per stage
    const int crow = tid >> 1;
    const int ck8  = (tid & 1) * 8;
    const long long ar = brow + crow;
    const long long br = bcol + crow;
    const int aval = (ar < Md) ? 16 : 0;
    const int bval = (br < Nd) ? 16 : 0;
    uint32_t smbase = (uint32_t)__cvta_generic_to_shared(smbuf);
    const uint32_t sa = smbase + (uint32_t)(crow * 12 + (ck8 >> 1)) * 4;
    const uint32_t sb = smbase + (uint32_t)(1536 + crow * 12 + (ck8 >> 1)) * 4;
    const __half* ga = A  + ar * lda + ck8;
    const __half* gb = Bt + br * ldb + ck8;

    float acc[4][4][4];
#pragma unroll
    for (int i = 0; i < 4; i++)
#pragma unroll
        for (int j = 0; j < 4; j++)
#pragma unroll
            for (int r = 0; r < 4; r++) acc[i][j][r] = 0.f;

    const int nt = Kd >> 4;

    // prologue: stages 0..2
#pragma unroll
    for (int s = 0; s < 3; s++) {
        uint32_t off = (uint32_t)s * 3072 * 4;
        int k0 = s * 16;
        asm volatile("cp.async.cg.shared.global [%0], [%1], 16, %2;"
                     :: "r"(sa + off), "l"(ga + k0), "r"(aval));
        asm volatile("cp.async.cg.shared.global [%0], [%1], 16, %2;"
                     :: "r"(sb + off), "l"(gb + k0), "r"(bval));
        asm volatile("cp.async.commit_group;");
    }

    // ldmatrix lane addressing
    const int a_row = wm * 64 + (lane & 15);
    const int a_kw  = (lane >> 4) * 4;
    const int b_row = wn * 32 + (lane & 7) + ((lane >> 4) << 3);
    const int b_kw  = ((lane >> 3) & 1) * 4;
    const uint32_t abase = smbase + (uint32_t)(a_row * 12 + a_kw) * 4;
    const uint32_t bbase = smbase + (uint32_t)(1536 + b_row * 12 + b_kw) * 4;

    for (int kt = 0; kt < nt; kt++) {
        asm volatile("cp.async.wait_group 2;");
        __syncthreads();
        uint32_t soff = (uint32_t)(kt & 3) * 3072 * 4;

        uint32_t af[4][4], bf[2][4];
#pragma unroll
        for (int mt = 0; mt < 4; mt++)
            asm volatile("ldmatrix.sync.aligned.m8n8.x4.shared.b16 {%0,%1,%2,%3}, [%4];"
                         : "=r"(af[mt][0]), "=r"(af[mt][1]), "=r"(af[mt][2]), "=r"(af[mt][3])
                         : "r"(abase + soff + (uint32_t)(mt * 16 * 12) * 4));
#pragma unroll
        for (int ng = 0; ng < 2; ng++)
            asm volatile("ldmatrix.sync.aligned.m8n8.x4.shared.b16 {%0,%1,%2,%3}, [%4];"
                         : "=r"(bf[ng][0]), "=r"(bf[ng][1]), "=r"(bf[ng][2]), "=r"(bf[ng][3])
                         : "r"(bbase + soff + (uint32_t)(ng * 16 * 12) * 4));

#pragma unroll
        for (int mt = 0; mt < 4; mt++)
#pragma unroll
            for (int j = 0; j < 4; j++)
                mma_f16(acc[mt][j],
                        af[mt][0], af[mt][1], af[mt][2], af[mt][3],
                        bf[j >> 1][(j & 1) * 2], bf[j >> 1][(j & 1) * 2 + 1]);

        int ktn = kt + 3;
        if (ktn < nt) {
            uint32_t doff = (uint32_t)(ktn & 3) * 3072 * 4;
            int k0 = ktn * 16;
            asm volatile("cp.async.cg.shared.global [%0], [%1], 16, %2;"
                         :: "r"(sa + doff), "l"(ga + k0), "r"(aval));
            asm volatile("cp.async.cg.shared.global [%0], [%1], 16, %2;"
                         :: "r"(sb + doff), "l"(gb + k0), "r"(bval));
        }
        asm volatile("cp.async.commit_group;");
    }

    // epilogue (Nd is even; c always even -> pair stores safe)
    float*  Cf = (float*)Cv;
    __half* Ch = (__half*)Cv;
#pragma unroll
    for (int mt = 0; mt < 4; mt++) {
#pragma unroll
        for (int hh = 0; hh < 2; hh++) {
            int r = brow + wm * 64 + mt * 16 + g + 8 * hh;
            if (r >= Md) continue;
#pragma unroll
            for (int j = 0; j < 4; j++) {
                int c = bcol + wn * 32 + j * 8 + 2 * q;
                if (c >= Nd) continue;
                float v0 = acc[mt][j][hh * 2];
                float v1 = acc[mt][j][hh * 2 + 1];
                v0 += bias[c]; v1 += bias[c + 1];
                if (EPI == EPI_BIAS_GELU) { v0 = gelu_tanh(v0); v1 = gelu_tanh(v1); }
                if (EPI == EPI_BIAS_RES)  {
                    v0 += Res[(long long)r * ldr + c];
                    v1 += Res[(long long)r * ldr + c + 1];
                }
                if (OUTH) {
                    __half2 hv = __floats2half2_rn(v0, v1);
                    *reinterpret_cast<__half2*>(Ch + (long long)r * ldc + c) = hv;
                } else {
                    *reinterpret_cast<float2*>(Cf + (long long)r * ldc + c) = make_float2(v0, v1);
                }
            }
        }
    }
}

// ---------------------------------------------------------------------------
// Fused flash attention, fp16 in/out, m16n8k16, online softmax (fp32 stats).
//   Same structure as R5 but reads fp16 qkv directly (no cvt) and writes fp16.
// ---------------------------------------------------------------------------
#define QS_OFF   0
#define QS_ST    44
#define KS_OFF   (QS_OFF + 128 * QS_ST)
#define KS_ST    72
#define VS_OFF   (KS_OFF + 40 * KS_ST)
#define VS_ST    104
#define PS_OFF   (VS_OFF + 32 * VS_ST)
#define PS_ST    36
#define MS_OFF   (PS_OFF + 128 * PS_ST)
#define LS_OFF   (MS_OFF + 128)
#define AL_OFF   (LS_OFF + 128)
#define RED_OFF  (AL_OFF + 128)
#define FA_WORDS (RED_OFF + 512)
#define FA_BYTES (FA_WORDS * 4)

__global__ void __launch_bounds__(256, 1)
flash_h(const __half* __restrict__ qkv, __half* __restrict__ attn)
{
    extern __shared__ uint32_t smem[];
    uint32_t* Qs = smem + QS_OFF;
    uint32_t* Ks = smem + KS_OFF;
    uint32_t* Vs = smem + VS_OFF;
    uint32_t* Ps = smem + PS_OFF;
    float* m_s  = (float*)(smem + MS_OFF);
    float* l_s  = (float*)(smem + LS_OFF);
    float* al_s = (float*)(smem + AL_OFF);
    float* red  = (float*)(smem + RED_OFF);

    int t = blockIdx.x;
    int head = blockIdx.y;
    int st, S, q0;
    if (t < 18)      { st = 0;    S = 2304; q0 = t * 128; }
    else if (t < 34) { st = 2304; S = 2048; q0 = (t - 18) * 128; }
    else if (t < 42) { st = 4352; S = 960;  q0 = (t - 34) * 128; }
    else             { st = 5312; S = 960;  q0 = (t - 42) * 128; }

    const int tid = threadIdx.x;
    const int w = tid >> 5, lane = tid & 31;
    const int g = lane >> 2, q = lane & 3;
    const int wm  = w & 1, wn  = w >> 1;   // QK 2(M) x 4(N)
    const int wm2 = w & 3, wn2 = w >> 2;   // PV 4(M) x 2(N)

    const float scale = 0.11785113019775793f;

    // ---- Q tile: 9 x uint4 per row (72 halfs)
    for (int s = tid; s < 128 * 9; s += 256) {
        int row = s / 9, w8 = s % 9;
        uint4 v = make_uint4(0, 0, 0, 0);
        if (q0 + row < S)
            v = *reinterpret_cast<const uint4*>(
                qkv + (size_t)(st + q0 + row) * QKVW + head * HDIM + w8 * 8);
        *reinterpret_cast<uint4*>(&Qs[row * QS_ST + w8 * 4]) = v;
    }
    for (int s = tid; s < 512; s += 256) {
        int row = s >> 2, kk = 36 + (s & 3);
        Qs[row * QS_ST + kk] = 0;
    }
    if (tid < 256) Ks[(36 + (tid >> 6)) * KS_ST + (tid & 63)] = 0;
    if (tid < 256) Vs[(tid >> 3) * VS_ST + 72 + (tid & 7)] = 0;
    if (tid < 128) { m_s[tid] = -1e30f; l_s[tid] = 0.f; }

    float O[2][5][4];
#pragma unroll
    for (int i = 0; i < 2; i++)
#pragma unroll
        for (int j = 0; j < 5; j++)
#pragma unroll
            for (int r = 0; r < 4; r++) O[i][j][r] = 0.f;

    const int nkv = S >> 6;
    for (int j = 0; j < nkv; j++) {
        __syncthreads();
        const int kv0 = j * 64;
        // K -> Ks[kk][kv]
        for (int s = tid; s < 64 * 9; s += 256) {
            int kv = s / 9, w8 = s % 9;
            uint4 v = *reinterpret_cast<const uint4*>(
                qkv + (size_t)(st + kv0 + kv) * QKVW + DMODEL + head * HDIM + w8 * 8);
            Ks[(w8 * 4 + 0) * KS_ST + kv] = v.x;
            Ks[(w8 * 4 + 1) * KS_ST + kv] = v.y;
            Ks[(w8 * 4 + 2) * KS_ST + kv] = v.z;
            Ks[(w8 * 4 + 3) * KS_ST + kv] = v.w;
        }
        // V -> Vs[kv/2][hd] halfword-interleaved
        for (int s = tid; s < 64 * 9; s += 256) {
            int kv = s / 9, w8 = s % 9;
            uint4 v = *reinterpret_cast<const uint4*>(
                qkv + (size_t)(st + kv0 + kv) * QKVW + 2 * DMODEL + head * HDIM + w8 * 8);
            uint16_t hx[8];
            *reinterpret_cast<uint4*>(hx) = v;
            uint16_t* Vh = reinterpret_cast<uint16_t*>(Vs);
            int base = ((kv >> 1) * VS_ST + w8 * 8) * 2 + (kv & 1);
#pragma unroll
            for (int i = 0; i < 8; i++) Vh[base + 2 * i] = hx[i];
        }
        __syncthreads();

        // ---- S = scale * Q @ K^T (5 k16 steps over padded 80)
        float acc_s[4][2][4];
#pragma unroll
        for (int a = 0; a < 4; a++)
#pragma unroll
            for (int b = 0; b < 2; b++)
#pragma unroll
                for (int r = 0; r < 4; r++) acc_s[a][b][r] = 0.f;

#pragma unroll
        for (int i = 0; i < 5; i++) {
            int kb = i * 8;
            uint32_t af[4][4], bf[2][2];
#pragma unroll
            for (int mt = 0; mt < 4; mt++) {
                int mb = wm * 64 + mt * 16;
                af[mt][0] = Qs[(mb + g    ) * QS_ST + kb + q    ];
                af[mt][1] = Qs[(mb + g + 8) * QS_ST + kb + q    ];
                af[mt][2] = Qs[(mb + g    ) * QS_ST + kb + q + 4];
                af[mt][3] = Qs[(mb + g + 8) * QS_ST + kb + q + 4];
            }
#pragma unroll
            for (int nt = 0; nt < 2; nt++) {
                int nb = wn * 16 + nt * 8;
                bf[nt][0] = Ks[(kb + q    ) * KS_ST + nb + g];
                bf[nt][1] = Ks[(kb + q + 4) * KS_ST + nb + g];
            }
#pragma unroll
            for (int mt = 0; mt < 4; mt++)
#pragma unroll
                for (int nt = 0; nt < 2; nt++)
                    mma_f16(acc_s[mt][nt],
                            af[mt][0], af[mt][1], af[mt][2], af[mt][3],
                            bf[nt][0], bf[nt][1]);
        }
#pragma unroll
        for (int a = 0; a < 4; a++)
#pragma unroll
            for (int b = 0; b < 2; b++)
#pragma unroll
                for (int r = 0; r < 4; r++) acc_s[a][b][r] *= scale;

        // ---- row max
#pragma unroll
        for (int mt = 0; mt < 4; mt++) {
#pragma unroll
            for (int h = 0; h < 2; h++) {
                float rmx = fmaxf(fmaxf(acc_s[mt][0][2 * h], acc_s[mt][0][2 * h + 1]),
                                  fmaxf(acc_s[mt][1][2 * h], acc_s[mt][1][2 * h + 1]));
                rmx = fmaxf(rmx, __shfl_xor_sync(0xffffffffu, rmx, 1));
                rmx = fmaxf(rmx, __shfl_xor_sync(0xffffffffu, rmx, 2));
                if (q == 0)
                    red[wn * 128 + wm * 64 + mt * 16 + g + 8 * h] = rmx;
            }
        }
        __syncthreads();
        if (tid < 128) {
            float tm = fmaxf(fmaxf(red[tid], red[128 + tid]),
                             fmaxf(red[256 + tid], red[384 + tid]));
            float mo = m_s[tid];
            float mn = fmaxf(mo, tm);
            al_s[tid] = __expf(mo - mn);
            m_s[tid]  = mn;
        }
        __syncthreads();

        // ---- P~ = exp(S - m) -> Ps; row sums
#pragma unroll
        for (int mt = 0; mt < 4; mt++) {
#pragma unroll
            for (int h = 0; h < 2; h++) {
                int row = wm * 64 + mt * 16 + g + 8 * h;
                float mn = m_s[row];
                float rs = 0.f;
#pragma unroll
                for (int nt = 0; nt < 2; nt++) {
                    int nb = wn * 16 + nt * 8;
                    float p0 = __expf(acc_s[mt][nt][2 * h    ] - mn);
                    float p1 = __expf(acc_s[mt][nt][2 * h + 1] - mn);
                    rs += p0 + p1;
                    Ps[row * PS_ST + (nb >> 1) + q] = pack_h2(p0, p1);
                }
                rs += __shfl_xor_sync(0xffffffffu, rs, 1);
                rs += __shfl_xor_sync(0xffffffffu, rs, 2);
                if (q == 0) red[wn * 128 + row] = rs;
            }
        }
        // rescale O
#pragma unroll
        for (int mt = 0; mt < 2; mt++) {
#pragma unroll
            for (int h = 0; h < 2; h++) {
                int row = wm2 * 32 + mt * 16 + g + 8 * h;
                float a = al_s[row];
#pragma unroll
                for (int nt = 0; nt < 5; nt++) {
                    O[mt][nt][2 * h + 0] *= a;
                    O[mt][nt][2 * h + 1] *= a;
                }
            }
        }
        __syncthreads();
        if (tid < 128)
            l_s[tid] = l_s[tid] * al_s[tid] +
                       red[tid] + red[128 + tid] + red[256 + tid] + red[384 + tid];

        // ---- O += P~ @ V
#pragma unroll
        for (int i = 0; i < 4; i++) {
            int kb = i * 8;
            uint32_t af[2][4], bf[5][2];
#pragma unroll
            for (int mt = 0; mt < 2; mt++) {
                int mb = wm2 * 32 + mt * 16;
                af[mt][0] = Ps[(mb + g    ) * PS_ST + kb + q    ];
                af[mt][1] = Ps[(mb + g + 8) * PS_ST + kb + q    ];
                af[mt][2] = Ps[(mb + g    ) * PS_ST + kb + q + 4];
                af[mt][3] = Ps[(mb + g + 8) * PS_ST + kb + q + 4];
            }
#pragma unroll
            for (int nt = 0; nt < 5; nt++) {
                int nb = wn2 * 40 + nt * 8;
                bf[nt][0] = Vs[(kb + q    ) * VS_ST + nb + g];
                bf[nt][1] = Vs[(kb + q + 4) * VS_ST + nb + g];
            }
#pragma unroll
            for (int mt = 0; mt < 2; mt++)
#pragma unroll
                for (int nt = 0; nt < 5; nt++)
                    mma_f16(O[mt][nt],
                            af[mt][0], af[mt][1], af[mt][2], af[mt][3],
                            bf[nt][0], bf[nt][1]);
        }
    }
    __syncthreads();

    // ---- epilogue: fp16 pair stores
#pragma unroll
    for (int mt = 0; mt < 2; mt++) {
#pragma unroll
        for (int h = 0; h < 2; h++) {
            int r = wm2 * 32 + mt * 16 + g + 8 * h;
            if (q0 + r >= S) continue;
            float inv = 1.0f / l_s[r];
#pragma unroll
            for (int nt = 0; nt < 5; nt++) {
                int c = wn2 * 40 + nt * 8 + 2 * q;
                if (c >= HDIM) continue;
                __half2 hv = __floats2half2_rn(O[mt][nt][2 * h] * inv,
                                               O[mt][nt][2 * h + 1] * inv);
                *reinterpret_cast<__half2*>(
                    attn + (size_t)(st + q0 + r) * DMODEL + head * HDIM + c) = hv;
            }
        }
    }
}

// ---------------------------------------------------------------------------
// Host launcher
// ---------------------------------------------------------------------------
#define SYMF(p, s) do { void* _t; cudaGetSymbolAddress(&_t, s); p = (float*)_t; } while (0)
#define SYMH(p, s) do { void* _t; cudaGetSymbolAddress(&_t, s); p = (__half*)_t; } while (0)

static inline dim3 ggrid3(int Md, int Nd) {
    return dim3((Nd + 127) / 128, (Md + 127) / 128);
}
static inline dim3 tgrid(int K, int N) {
    return dim3((N + 31) / 32, (K + 31) / 32);
}

extern "C" void kernel_launch(void* const* d_in, const int* in_sizes, int n_in,
                              void* d_out, int out_size)
{
    (void)in_sizes; (void)n_in; (void)out_size;
    const float* pixel    = (const float*)d_in[0];
    const float* patch_w  = (const float*)d_in[2];
    const float* patch_b  = (const float*)d_in[3];
    const float* pos_tab  = (const float*)d_in[4];
    const float* ln1_s    = (const float*)d_in[5];
    const float* ln1_b    = (const float*)d_in[6];
    const float* qkv_w    = (const float*)d_in[7];
    const float* qkv_b    = (const float*)d_in[8];
    const float* proj_w   = (const float*)d_in[9];
    const float* proj_b   = (const float*)d_in[10];
    const float* ln2_s    = (const float*)d_in[11];
    const float* ln2_b    = (const float*)d_in[12];
    const float* fc1_w    = (const float*)d_in[13];
    const float* fc1_b    = (const float*)d_in[14];
    const float* fc2_w    = (const float*)d_in[15];
    const float* fc2_b    = (const float*)d_in[16];
    const float* m_ln_s   = (const float*)d_in[17];
    const float* m_ln_b   = (const float*)d_in[18];
    const float* m_fc1_w  = (const float*)d_in[19];
    const float* m_fc1_b  = (const float*)d_in[20];
    const float* m_fc2_w  = (const float*)d_in[21];
    const float* m_fc2_b  = (const float*)d_in[22];
    float* out = (float*)d_out;

    float *x;
    __half *pix, *hh, *qkvh, *attnh, *mlph, *wt;
    SYMF(x, g_x);
    SYMH(pix, g_pix); SYMH(hh, g_hh); SYMH(qkvh, g_qkvh);
    SYMH(attnh, g_attnh); SYMH(mlph, g_mlph); SYMH(wt, g_wt);

    static bool attr_set = false;
    if (!attr_set) {
        cudaFuncSetAttribute(flash_h,
                             cudaFuncAttributeMaxDynamicSharedMemorySize, FA_BYTES);
        attr_set = true;
    }

    // ---- weight conversion / transposition (device-side, every replay)
    conv_h<<<(NTOK * CIN + 255) / 256, 256>>>(pixel, pix, NTOK * CIN);
    wt_t<<<tgrid(CIN, DMODEL), dim3(32, 8)>>>(patch_w, wt + OFF_PATCH, CIN, DMODEL);
    for (int l = 0; l < 2; l++) {
        wt_t<<<tgrid(DMODEL, QKVW), dim3(32, 8)>>>(
            qkv_w + (size_t)l * DMODEL * QKVW, wt + OFF_QKV + l * SZ_QKV, DMODEL, QKVW);
        wt_t<<<tgrid(DMODEL, DMODEL), dim3(32, 8)>>>(
            proj_w + (size_t)l * DMODEL * DMODEL, wt + OFF_PROJ + l * SZ_PROJ, DMODEL, DMODEL);
        wt_t<<<tgrid(DMODEL, IDIM), dim3(32, 8)>>>(
            fc1_w + (size_t)l * DMODEL * IDIM, wt + OFF_FC1 + l * SZ_FC1, DMODEL, IDIM);
        wt_t<<<tgrid(IDIM, DMODEL), dim3(32, 8)>>>(
            fc2_w + (size_t)l * IDIM * DMODEL, wt + OFF_FC2 + l * SZ_FC2, IDIM, DMODEL);
    }
    wt_t<<<tgrid(MD4, MD4), dim3(32, 8)>>>(m_fc1_w, wt + OFF_MFC1, MD4, MD4);
    wt_t<<<tgrid(MD4, DOUT), dim3(32, 8)>>>(m_fc2_w, wt + OFF_MFC2, MD4, DOUT);

    cossin_kernel<<<(NTOK * 36 + 255) / 256, 256>>>();

    // Patch embed -> x (fp32)
    gemm3<EPI_BIAS, false><<<ggrid3(NTOK, DMODEL), 256>>>(
        pix, CIN, wt + OFF_PATCH, CIN, x, DMODEL,
        patch_b, nullptr, 0, NTOK, DMODEL, CIN);

    posadd_kernel<<<NTOK, 288>>>(pos_tab);

    for (int l = 0; l < 2; l++) {
        ln_h<<<NTOK, 288>>>(x, hh, ln1_s + l * DMODEL, ln1_b + l * DMODEL);

        gemm3<EPI_BIAS, true><<<ggrid3(NTOK, QKVW), 256>>>(
            hh, DMODEL, wt + OFF_QKV + l * SZ_QKV, DMODEL, qkvh, QKVW,
            qkv_b + (size_t)l * QKVW, nullptr, 0, NTOK, QKVW, DMODEL);

        rope_h<<<NTOK, 576>>>();

        flash_h<<<dim3(50, HEADS), 256, FA_BYTES>>>(qkvh, attnh);

        gemm3<EPI_BIAS_RES, false><<<ggrid3(NTOK, DMODEL), 256>>>(
            attnh, DMODEL, wt + OFF_PROJ + l * SZ_PROJ, DMODEL, x, DMODEL,
            proj_b + (size_t)l * DMODEL, x, DMODEL, NTOK, DMODEL, DMODEL);

        ln_h<<<NTOK, 288>>>(x, hh, ln2_s + l * DMODEL, ln2_b + l * DMODEL);

        gemm3<EPI_BIAS_GELU, true><<<ggrid3(NTOK, IDIM), 256>>>(
            hh, DMODEL, wt + OFF_FC1 + l * SZ_FC1, DMODEL, mlph, IDIM,
            fc1_b + (size_t)l * IDIM, nullptr, 0, NTOK, IDIM, DMODEL);

        gemm3<EPI_BIAS_RES, false><<<ggrid3(NTOK, DMODEL), 256>>>(
            mlph, IDIM, wt + OFF_FC2 + l * SZ_FC2, IDIM, x, DMODEL,
            fc2_b + (size_t)l * DMODEL, x, DMODEL, NTOK, DMODEL, IDIM);
    }

    // merger
    ln_h<<<NTOK, 288>>>(x, hh, m_ln_s, m_ln_b);   // hh viewed as [1568][4608]

    gemm3<EPI_BIAS_GELU, true><<<ggrid3(MROWS, MD4), 256>>>(
        hh, MD4, wt + OFF_MFC1, MD4, mlph, MD4,
        m_fc1_b, nullptr, 0, MROWS, MD4, MD4);

    gemm3<EPI_BIAS, false><<<ggrid3(MROWS, DOUT), 256>>>(
        mlph, MD4, wt + OFF_MFC2, MD4, out, DOUT,
        m_fc2_b, nullptr, 0, MROWS, DOUT, MD4);
}